// round 12
// baseline (speedup 1.0000x reference)
#include <cuda_runtime.h>
#include <cuda_fp16.h>

// Sinkhorn on s[B=32, N=1024, M=1024], MAX_ITER=15, EPS=1e-4.
//
// Single persistent kernel. Factored form s_t = r_i * s0_ij * c_j.
// KEY: the row step (it=2h+1) and col step (it=2h+2) are fused into ONE
// matrix sweep: per row, stage the row in registers, compute q_i = sum h*c,
// derive r_i (butterfly broadcast), then accumulate r_i*h into per-lane
// column accumulators from the SAME registers. 16 matrix passes -> 9.
//
// grid = 128 blocks (4 per batch, 256 rows each), 512 threads, 1 block/SM
// (one wave; spin barrier safe). Cross-warp column reduction via smem tree.

#define BB 32
#define NN 1024
#define MM 1024
#define EPSF 1e-4f
#define KB_ 4             // blocks per batch
#define RPB 256           // rows per block
#define TPB 512

__device__ __half2 g_h[(size_t)BB * NN * MM / 2];   // 64 MB fp16 copy
__device__ float g_part[2][BB * KB_ * MM];          // double-buffered partials
__device__ int g_cnt2[BB];                          // zero-init
__device__ int g_flag[BB];                          // monotonic, persists

// ---------------------------------------------------------------------------
__device__ __forceinline__ void batch_barrier(int b, int& nextv) {
    __threadfence();
    __syncthreads();
    nextv += 1;
    if (threadIdx.x == 0) {
        int old = atomicAdd(&g_cnt2[b], 1);
        if (old == KB_ - 1) {
            atomicExch(&g_cnt2[b], 0);
            __threadfence();
            *(volatile int*)&g_flag[b] = nextv;
        } else {
            while (*(volatile int*)&g_flag[b] - nextv < 0) __nanosleep(32);
        }
        __threadfence();
    }
    __syncthreads();
}

#define DECODE4(V, F0, F1, F2, F3)                  \
    float2 F0 = __half22float2(*(__half2*)&(V).x);  \
    float2 F1 = __half22float2(*(__half2*)&(V).y);  \
    float2 F2 = __half22float2(*(__half2*)&(V).z);  \
    float2 F3 = __half22float2(*(__half2*)&(V).w);

// dot of one uint4 (8 halfs at cols [(KK*32+lane)*8 ...]) with c in smem
#define DOT8(V, KK, Q0, Q1)                                      \
    do {                                                         \
        DECODE4(V, f0, f1, f2, f3);                              \
        const float4 ca = *(const float4*)&sc[((KK)*32 + lane) * 8];     \
        const float4 cb = *(const float4*)&sc[((KK)*32 + lane) * 8 + 4]; \
        Q0 = fmaf(f0.x, ca.x, Q0);                               \
        Q1 = fmaf(f0.y, ca.y, Q1);                               \
        Q0 = fmaf(f1.x, ca.z, Q0);                               \
        Q1 = fmaf(f1.y, ca.w, Q1);                               \
        Q0 = fmaf(f2.x, cb.x, Q0);                               \
        Q1 = fmaf(f2.y, cb.y, Q1);                               \
        Q0 = fmaf(f3.x, cb.z, Q0);                               \
        Q1 = fmaf(f3.y, cb.w, Q1);                               \
    } while (0)

// accumulate R * (8 halfs of V) into acc[KK*8 .. KK*8+8)
#define ACC8(V, R, KK)                                  \
    do {                                                \
        DECODE4(V, f0, f1, f2, f3);                     \
        acc[(KK)*8 + 0] = fmaf(R, f0.x, acc[(KK)*8 + 0]); \
        acc[(KK)*8 + 1] = fmaf(R, f0.y, acc[(KK)*8 + 1]); \
        acc[(KK)*8 + 2] = fmaf(R, f1.x, acc[(KK)*8 + 2]); \
        acc[(KK)*8 + 3] = fmaf(R, f1.y, acc[(KK)*8 + 3]); \
        acc[(KK)*8 + 4] = fmaf(R, f2.x, acc[(KK)*8 + 4]); \
        acc[(KK)*8 + 5] = fmaf(R, f2.y, acc[(KK)*8 + 5]); \
        acc[(KK)*8 + 6] = fmaf(R, f3.x, acc[(KK)*8 + 6]); \
        acc[(KK)*8 + 7] = fmaf(R, f3.y, acc[(KK)*8 + 7]); \
    } while (0)

// ---------------------------------------------------------------------------
__global__ void __launch_bounds__(TPB, 1)
sinkhorn_kernel(const float* __restrict__ s, float* __restrict__ out) {
    const int bx = blockIdx.x;
    const int b = bx >> 2;         // batch
    const int k = bx & (KB_ - 1);  // block within batch
    const int tid = threadIdx.x;
    const int warp = tid >> 5;     // 0..15
    const int lane = tid & 31;

    __shared__ __align__(16) float sc[MM];       // 4 KB column scaling
    __shared__ float sr[RPB];                    // 1 KB row scaling
    __shared__ __align__(16) float sacc[8][MM];  // 32 KB col-reduce tree

    int nextv = *(volatile int*)&g_flag[b];

    const size_t brow0 = (size_t)b * NN + (size_t)k * RPB;
    const int half = tid >> 8;     // 0/1 for conv+finalize split
    const int ct = tid & 255;
    const size_t hrow0 = brow0 + half * 128;

    // ---------------- it = 0: fp32->fp16 conversion + column partials (r=1)
    {
        const float4* sp = (const float4*)s + hrow0 * (MM / 4) + ct;
        uint2* hw = (uint2*)g_h + hrow0 * (MM / 4) + ct;
        float4 a = make_float4(0.f, 0.f, 0.f, 0.f);
#pragma unroll 4
        for (int i = 0; i < 128; i++) {
            float4 v = sp[(size_t)i * (MM / 4)];
            __half2 h0 = __floats2half2_rn(v.x, v.y);
            __half2 h1 = __floats2half2_rn(v.z, v.w);
            uint2 o;
            o.x = *(unsigned*)&h0;
            o.y = *(unsigned*)&h1;
            hw[(size_t)i * (MM / 4)] = o;
            a.x += v.x; a.y += v.y; a.z += v.z; a.w += v.w;
        }
        if (half) *(float4*)&sacc[0][ct * 4] = a;
        __syncthreads();
        if (!half) {
            float4 o2 = *(float4*)&sacc[0][ct * 4];
            a.x += o2.x; a.y += o2.y; a.z += o2.z; a.w += o2.w;
            *(float4*)&g_part[0][((size_t)(b * KB_ + k)) * MM + ct * 4] = a;
        }
    }
    batch_barrier(b, nextv);

    // c init (c_old = 1): thread owns 2 cols.
    {
        const int j2 = tid * 2;
        float p0 = 0.f, p1 = 0.f;
#pragma unroll
        for (int q = 0; q < KB_; q++) {
            float2 v = __ldcg(
                (const float2*)&g_part[0][((size_t)(b * KB_ + q)) * MM + j2]);
            p0 += v.x; p1 += v.y;
        }
        sc[j2] = 1.0f / (p0 + EPSF);
        sc[j2 + 1] = 1.0f / (p1 + EPSF);
    }
    __syncthreads();

    const uint4* h4 = (const uint4*)g_h;  // row stride MM/8 = 128

    // ---------------- 7 x fused (row it=2h+1 + col it=2h+2) in ONE sweep
    for (int hh = 0; hh < 7; hh++) {
        float acc[32];
#pragma unroll
        for (int e = 0; e < 32; e++) acc[e] = 0.f;

        const int rbase = warp * 16;  // warp owns 16 rows
#pragma unroll 1
        for (int ip = 0; ip < 8; ip++) {
            const int i0 = rbase + ip * 2;
            const uint4* p0 = h4 + (brow0 + i0) * (MM / 8) + lane;
            const uint4* p1 = p0 + (MM / 8);
            uint4 va0 = p0[0], va1 = p0[32], va2 = p0[64], va3 = p0[96];
            uint4 vb0 = p1[0], vb1 = p1[32], vb2 = p1[64], vb3 = p1[96];

            float qa0 = 0.f, qa1 = 0.f, qb0 = 0.f, qb1 = 0.f;
            DOT8(va0, 0, qa0, qa1);
            DOT8(va1, 1, qa0, qa1);
            DOT8(va2, 2, qa0, qa1);
            DOT8(va3, 3, qa0, qa1);
            DOT8(vb0, 0, qb0, qb1);
            DOT8(vb1, 1, qb0, qb1);
            DOT8(vb2, 2, qb0, qb1);
            DOT8(vb3, 3, qb0, qb1);
            float qa = qa0 + qa1;
            float qb = qb0 + qb1;
#pragma unroll
            for (int o = 16; o > 0; o >>= 1) {
                qa += __shfl_xor_sync(0xffffffffu, qa, o);
                qb += __shfl_xor_sync(0xffffffffu, qb, o);
            }
            float r0o = (hh == 0) ? 1.0f : sr[i0];
            float r1o = (hh == 0) ? 1.0f : sr[i0 + 1];
            float r0 = r0o / fmaf(r0o, qa, EPSF);
            float r1 = r1o / fmaf(r1o, qb, EPSF);
            if (lane == 0) {
                sr[i0] = r0;
                sr[i0 + 1] = r1;
            }
            ACC8(va0, r0, 0);
            ACC8(va1, r0, 1);
            ACC8(va2, r0, 2);
            ACC8(va3, r0, 3);
            ACC8(vb0, r1, 0);
            ACC8(vb1, r1, 1);
            ACC8(vb2, r1, 2);
            ACC8(vb3, r1, 3);
        }

        // ---- cross-warp column reduction (fixed order, deterministic)
        if (warp >= 8) {
#pragma unroll
            for (int kk = 0; kk < 4; kk++) {
                const int cb = (kk * 32 + lane) * 8;
                *(float4*)&sacc[warp - 8][cb] =
                    make_float4(acc[kk * 8 + 0], acc[kk * 8 + 1],
                                acc[kk * 8 + 2], acc[kk * 8 + 3]);
                *(float4*)&sacc[warp - 8][cb + 4] =
                    make_float4(acc[kk * 8 + 4], acc[kk * 8 + 5],
                                acc[kk * 8 + 6], acc[kk * 8 + 7]);
            }
        }
        __syncthreads();
        if (warp < 8) {
#pragma unroll
            for (int kk = 0; kk < 4; kk++) {
                const int cb = (kk * 32 + lane) * 8;
                float4 u = *(float4*)&sacc[warp][cb];
                float4 w = *(float4*)&sacc[warp][cb + 4];
                u.x += acc[kk * 8 + 0]; u.y += acc[kk * 8 + 1];
                u.z += acc[kk * 8 + 2]; u.w += acc[kk * 8 + 3];
                w.x += acc[kk * 8 + 4]; w.y += acc[kk * 8 + 5];
                w.z += acc[kk * 8 + 6]; w.w += acc[kk * 8 + 7];
                *(float4*)&sacc[warp][cb] = u;
                *(float4*)&sacc[warp][cb + 4] = w;
            }
        }
        __syncthreads();

        const int buf = (hh + 1) & 1;
        {
            const int j2 = tid * 2;
            float p0 = 0.f, p1 = 0.f;
#pragma unroll
            for (int w = 0; w < 8; w++) {
                p0 += sacc[w][j2];
                p1 += sacc[w][j2 + 1];
            }
            *(float2*)&g_part[buf][((size_t)(b * KB_ + k)) * MM + j2] =
                make_float2(p0, p1);
        }
        batch_barrier(b, nextv);

        // ---- c update (all blocks, identical fixed order)
        {
            const int j2 = tid * 2;
            float p0 = 0.f, p1 = 0.f;
#pragma unroll
            for (int q = 0; q < KB_; q++) {
                float2 v = __ldcg((const float2*)
                    &g_part[buf][((size_t)(b * KB_ + q)) * MM + j2]);
                p0 += v.x; p1 += v.y;
            }
            float c0 = sc[j2];
            float c1 = sc[j2 + 1];
            sc[j2] = c0 / fmaf(c0, p0, EPSF);
            sc[j2 + 1] = c1 / fmaf(c1, p1, EPSF);
        }
        __syncthreads();
    }

    // ---------------- finalize: out = r_i * h_ij * c_j (fp16 copy, L2-hot)
    {
        const uint2* hp = (const uint2*)g_h + hrow0 * (MM / 4) + ct;
        float4* op = (float4*)out + hrow0 * (MM / 4) + ct;
        const float4 c4 = *(float4*)&sc[ct * 4];
        const float* srh = sr + half * 128;
#pragma unroll 4
        for (int i = 0; i < 128; i++) {
            const float r = srh[i];
            uint2 v = hp[(size_t)i * (MM / 4)];
            float2 f0 = __half22float2(*(__half2*)&v.x);
            float2 f1 = __half22float2(*(__half2*)&v.y);
            float4 o;
            o.x = r * f0.x * c4.x;
            o.y = r * f0.y * c4.y;
            o.z = r * f1.x * c4.z;
            o.w = r * f1.y * c4.w;
            op[(size_t)i * (MM / 4)] = o;
        }
    }
}

// ---------------------------------------------------------------------------
extern "C" void kernel_launch(void* const* d_in, const int* in_sizes, int n_in,
                              void* d_out, int out_size) {
    const float* s = (const float*)d_in[0];
    float* out = (float*)d_out;
    sinkhorn_kernel<<<BB * KB_, TPB>>>(s, out);
}

// round 13
// speedup vs baseline: 1.2513x; 1.2513x over previous
#include <cuda_runtime.h>
#include <cuda_fp16.h>

// Sinkhorn on s[B=32, N=1024, M=1024], MAX_ITER=15, EPS=1e-4.
//
// Single persistent kernel (R10 structure). Factored form
// s_t = r_i * s0_ij * c_j. 512-thread blocks; block k of batch b owns rows
// [128k, 128k+128); halves own 64 rows each with R5's validated loop bodies.
//
// R13 delta: batch = CGA cluster of 8 CTAs. The software monotonic barrier
// is replaced by hardware barrier.cluster.arrive(release)/wait(acquire),
// which also provides the memory ordering for the g_part exchange.
// Batches are cluster-local, so correctness is wave-count independent.

#define BB 32
#define NN 1024
#define MM 1024
#define EPSF 1e-4f
#define KB_ 8             // blocks per batch = cluster size
#define RPB (NN / KB_)    // 128 rows per block
#define HROWS 64          // rows per half
#define TPB 512

__device__ __half2 g_h[(size_t)BB * NN * MM / 2];   // 64 MB fp16 copy
__device__ float g_part[2][BB * KB_ * MM];          // double-buffered partials

// Hardware cluster barrier: arrive has release, wait has acquire semantics,
// so g_part writes before the barrier are visible to cluster peers after it.
__device__ __forceinline__ void cluster_barrier() {
    asm volatile("barrier.cluster.arrive.aligned;" ::: "memory");
    asm volatile("barrier.cluster.wait.aligned;" ::: "memory");
}

// ---------------------------------------------------------------------------
__global__ void __launch_bounds__(TPB, 2) __cluster_dims__(KB_, 1, 1)
sinkhorn_kernel(const float* __restrict__ s, float* __restrict__ out) {
    const int bx = blockIdx.x;
    const int b = bx >> 3;         // batch (== cluster id)
    const int k = bx & (KB_ - 1);  // block within batch (== cluster rank)
    const int tid = threadIdx.x;
    const int half = tid >> 8;     // 0 or 1
    const int ct = tid & 255;      // column group: owns cols [4ct, 4ct+4)

    __shared__ float sc[MM];       // column scaling c (full vector)
    __shared__ float sr[RPB];      // row scaling r (own 128 rows)
    __shared__ float scomb[MM];    // half-combine buffer (4 KB)

    // this half's first row (global)
    const size_t hrow0 = (size_t)(b * NN + k * RPB + half * HROWS);

    // ---------------- it = 0: fp32->fp16 conversion + column partials (r=1)
    {
        const float4* sp = (const float4*)(s + hrow0 * MM) + ct;
        __half2* hp = g_h + hrow0 * (MM / 2) + ct * 2;
        float4 acc = make_float4(0.f, 0.f, 0.f, 0.f);
#pragma unroll 4
        for (int i = 0; i < HROWS; i++) {
            float4 v = sp[(size_t)i * (MM / 4)];
            __half2 h0 = __floats2half2_rn(v.x, v.y);
            __half2 h1 = __floats2half2_rn(v.z, v.w);
            uint2 o;
            o.x = *(unsigned*)&h0;
            o.y = *(unsigned*)&h1;
            *(uint2*)(hp + (size_t)i * (MM / 2)) = o;
            acc.x += v.x; acc.y += v.y; acc.z += v.z; acc.w += v.w;
        }
        if (half) *(float4*)&scomb[ct * 4] = acc;
        __syncthreads();
        if (!half) {
            float4 o2 = *(float4*)&scomb[ct * 4];
            acc.x += o2.x; acc.y += o2.y; acc.z += o2.z; acc.w += o2.w;
            *(float4*)&g_part[0][((size_t)(b * KB_ + k)) * MM + ct * 4] = acc;
        }
    }
    cluster_barrier();

    // c init (c_old = 1): split reduce across halves; half1 sums q=4..7.
    {
        const int j = ct * 4;
        float4 p = make_float4(0.f, 0.f, 0.f, 0.f);
#pragma unroll
        for (int q = 0; q < KB_ / 2; q++) {
            const int qq = half * (KB_ / 2) + q;
            const float4 v = __ldcg(
                (const float4*)&g_part[0][((size_t)(b * KB_ + qq)) * MM + j]);
            p.x += v.x; p.y += v.y; p.z += v.z; p.w += v.w;
        }
        if (half) *(float4*)&scomb[j] = p;
        __syncthreads();
        if (!half) {
            float4 o2 = *(float4*)&scomb[j];
            p.x += o2.x; p.y += o2.y; p.z += o2.z; p.w += o2.w;
            sc[j + 0] = 1.0f / (p.x + EPSF);
            sc[j + 1] = 1.0f / (p.y + EPSF);
            sc[j + 2] = 1.0f / (p.z + EPSF);
            sc[j + 3] = 1.0f / (p.w + EPSF);
        }
    }
    __syncthreads();

    // ---------------- 7 x (row step it=2h+1, col step it=2h+2)
    const int warp = tid >> 5;     // 0..15
    const int lane = tid & 31;
    const size_t brow0 = (size_t)(b * NN + k * RPB);  // block's first row

    for (int hh = 0; hh < 7; hh++) {
        // ---- row step: warp w handles rows [8w, 8w+8) of the 128-row slice
#pragma unroll
        for (int rr = 0; rr < RPB / 16; rr++) {   // 8 rows per warp
            const int i = warp * (RPB / 16) + rr;
            const uint4* hp = (const uint4*)(g_h + (brow0 + i) * (MM / 2));
            float acc = 0.f;
#pragma unroll
            for (int kk = 0; kk < 4; kk++) {
                int v4 = kk * 32 + lane;
                uint4 v = hp[v4];
                int jj = v4 * 8;
                float2 f0 = __half22float2(*(__half2*)&v.x);
                float2 f1 = __half22float2(*(__half2*)&v.y);
                float2 f2 = __half22float2(*(__half2*)&v.z);
                float2 f3 = __half22float2(*(__half2*)&v.w);
                acc = fmaf(f0.x, sc[jj + 0], acc);
                acc = fmaf(f0.y, sc[jj + 1], acc);
                acc = fmaf(f1.x, sc[jj + 2], acc);
                acc = fmaf(f1.y, sc[jj + 3], acc);
                acc = fmaf(f2.x, sc[jj + 4], acc);
                acc = fmaf(f2.y, sc[jj + 5], acc);
                acc = fmaf(f3.x, sc[jj + 6], acc);
                acc = fmaf(f3.y, sc[jj + 7], acc);
            }
#pragma unroll
            for (int o = 16; o > 0; o >>= 1)
                acc += __shfl_xor_sync(0xffffffffu, acc, o);
            if (lane == 0) {
                float r = (hh == 0) ? 1.0f : sr[i];
                sr[i] = r / fmaf(r, acc, EPSF);
            }
        }
        __syncthreads();

        // ---- col step partials: P_j += r_i * h_ij over this half's 64 rows
        const int buf = (hh + 1) & 1;
        {
            const uint2* hp = (const uint2*)(g_h + hrow0 * (MM / 2)) + ct;
            const float* srh = sr + half * HROWS;
            float4 acc = make_float4(0.f, 0.f, 0.f, 0.f);
#pragma unroll 8
            for (int i = 0; i < HROWS; i++) {
                uint2 v = hp[(size_t)i * (MM / 4)];
                float rw = srh[i];
                float2 f0 = __half22float2(*(__half2*)&v.x);
                float2 f1 = __half22float2(*(__half2*)&v.y);
                acc.x = fmaf(rw, f0.x, acc.x);
                acc.y = fmaf(rw, f0.y, acc.y);
                acc.z = fmaf(rw, f1.x, acc.z);
                acc.w = fmaf(rw, f1.y, acc.w);
            }
            if (half) *(float4*)&scomb[ct * 4] = acc;
            __syncthreads();
            if (!half) {
                float4 o2 = *(float4*)&scomb[ct * 4];
                acc.x += o2.x; acc.y += o2.y; acc.z += o2.z; acc.w += o2.w;
                *(float4*)&g_part[buf][((size_t)(b * KB_ + k)) * MM + ct * 4] =
                    acc;
            }
        }
        cluster_barrier();

        // ---- reduce partials -> c update (per block; split across halves)
        {
            const int j = ct * 4;
            float4 p = make_float4(0.f, 0.f, 0.f, 0.f);
#pragma unroll
            for (int q = 0; q < KB_ / 2; q++) {
                const int qq = half * (KB_ / 2) + q;
                const float4 v = __ldcg((const float4*)
                    &g_part[buf][((size_t)(b * KB_ + qq)) * MM + j]);
                p.x += v.x; p.y += v.y; p.z += v.z; p.w += v.w;
            }
            if (half) *(float4*)&scomb[j] = p;
            __syncthreads();
            if (!half) {
                float4 o2 = *(float4*)&scomb[j];
                p.x += o2.x; p.y += o2.y; p.z += o2.z; p.w += o2.w;
                float4 c = *(float4*)&sc[j];
                c.x = c.x / fmaf(c.x, p.x, EPSF);
                c.y = c.y / fmaf(c.y, p.y, EPSF);
                c.z = c.z / fmaf(c.z, p.z, EPSF);
                c.w = c.w / fmaf(c.w, p.w, EPSF);
                *(float4*)&sc[j] = c;
            }
        }
        __syncthreads();
    }

    // ---------------- finalize: out = r_i * h_ij * c_j (fp16 copy, L2-hot)
    {
        const int j = ct * 4;
        const float4 c4 = *(float4*)&sc[j];
        const float* srh = sr + half * HROWS;
        const uint2* hp = (const uint2*)(g_h + hrow0 * (MM / 2)) + ct;
        float4* op = (float4*)(out + hrow0 * MM) + ct;
#pragma unroll 4
        for (int i = 0; i < HROWS; i++) {
            const float r = srh[i];
            uint2 v = hp[(size_t)i * (MM / 4)];
            float2 f0 = __half22float2(*(__half2*)&v.x);
            float2 f1 = __half22float2(*(__half2*)&v.y);
            float4 o;
            o.x = r * f0.x * c4.x;
            o.y = r * f0.y * c4.y;
            o.z = r * f1.x * c4.z;
            o.w = r * f1.y * c4.w;
            op[(size_t)i * (MM / 4)] = o;
        }
    }
}

// ---------------------------------------------------------------------------
extern "C" void kernel_launch(void* const* d_in, const int* in_sizes, int n_in,
                              void* d_out, int out_size) {
    const float* s = (const float*)d_in[0];
    float* out = (float*)d_out;
    sinkhorn_kernel<<<BB * KB_, TPB>>>(s, out);
}